// round 3
// baseline (speedup 1.0000x reference)
#include <cuda_runtime.h>
#include <cuda_bf16.h>
#include <math.h>

#define B_   32
#define T_   2048
#define D_   1024
#define MEM_ 64
#define HID_ 512   // D/2
#define TS_  8     // time splits in mean kernel

// ---------------- device scratch (no allocations allowed) ----------------
__device__ __align__(16) float g_part[TS_ * B_ * D_];  // mean partials [ts][b][d]
__device__ __align__(16) float g_pxp [8 * B_ * D_];    // xp partials   [ks][b][e]
__device__ __align__(16) float g_ph  [16 * B_ * HID_]; // h partials    [ks][b][j]

// ---------------- KA: mean over T, partial sums ----------------
// grid (8 tsplits, 32 batches), 256 threads; thread owns 4 d-cols (float4),
// 8 independent loads + 8 accumulator chains in flight.
__global__ __launch_bounds__(256) void kA_mean(const float* __restrict__ x) {
    int ts = blockIdx.x;   // 0..7
    int b  = blockIdx.y;   // 0..31
    int tid = threadIdx.x;
    const float4* p = (const float4*)(x + ((size_t)b * T_ + (size_t)ts * 256) * D_) + tid;
    float4 a0 = {0,0,0,0}, a1 = a0, a2 = a0, a3 = a0, a4 = a0, a5 = a0, a6 = a0, a7 = a0;
    for (int t = 0; t < 256; t += 8) {
        float4 v0 = p[(t + 0) * (D_/4)];
        float4 v1 = p[(t + 1) * (D_/4)];
        float4 v2 = p[(t + 2) * (D_/4)];
        float4 v3 = p[(t + 3) * (D_/4)];
        float4 v4 = p[(t + 4) * (D_/4)];
        float4 v5 = p[(t + 5) * (D_/4)];
        float4 v6 = p[(t + 6) * (D_/4)];
        float4 v7 = p[(t + 7) * (D_/4)];
        a0.x += v0.x; a0.y += v0.y; a0.z += v0.z; a0.w += v0.w;
        a1.x += v1.x; a1.y += v1.y; a1.z += v1.z; a1.w += v1.w;
        a2.x += v2.x; a2.y += v2.y; a2.z += v2.z; a2.w += v2.w;
        a3.x += v3.x; a3.y += v3.y; a3.z += v3.z; a3.w += v3.w;
        a4.x += v4.x; a4.y += v4.y; a4.z += v4.z; a4.w += v4.w;
        a5.x += v5.x; a5.y += v5.y; a5.z += v5.z; a5.w += v5.w;
        a6.x += v6.x; a6.y += v6.y; a6.z += v6.z; a6.w += v6.w;
        a7.x += v7.x; a7.y += v7.y; a7.z += v7.z; a7.w += v7.w;
    }
    float4 s;
    s.x = ((a0.x + a1.x) + (a2.x + a3.x)) + ((a4.x + a5.x) + (a6.x + a7.x));
    s.y = ((a0.y + a1.y) + (a2.y + a3.y)) + ((a4.y + a5.y) + (a6.y + a7.y));
    s.z = ((a0.z + a1.z) + (a2.z + a3.z)) + ((a4.z + a5.z) + (a6.z + a7.z));
    s.w = ((a0.w + a1.w) + (a2.w + a3.w)) + ((a4.w + a5.w) + (a6.w + a7.w));
    ((float4*)g_part)[(ts * B_ + b) * (D_/4) + tid] = s;
}

// ---------------- KB: xp split-K GEMM, mean-finalize fused into A-load ----------------
// xp[b,e] = sum_d mean[b,d]*W[e,d];  grid (16 e-tiles of 64, 8 k-splits of 128)
__global__ __launch_bounds__(256) void kB_gemm_xp(const float* __restrict__ W) {
    __shared__ float As[B_][129];
    __shared__ float Ws[64][129];
    int et = blockIdx.x, ks = blockIdx.y;
    int e0 = et * 64, k0 = ks * 128;
    int tid = threadIdx.x;
    {   // load A 32x128, reducing 8 time-partials, * 1/T
        int bb  = tid >> 3;          // 0..31
        int kk0 = (tid & 7) * 16;    // 4 float4 per thread
        float4 acc[4] = {{0,0,0,0},{0,0,0,0},{0,0,0,0},{0,0,0,0}};
        #pragma unroll
        for (int ts = 0; ts < TS_; ts++) {
            const float4* src = (const float4*)(g_part + ((size_t)ts * B_ + bb) * D_ + k0 + kk0);
            #pragma unroll
            for (int j = 0; j < 4; j++) {
                float4 v = src[j];
                acc[j].x += v.x; acc[j].y += v.y; acc[j].z += v.z; acc[j].w += v.w;
            }
        }
        const float invT = 1.0f / (float)T_;
        #pragma unroll
        for (int j = 0; j < 4; j++) {
            As[bb][kk0 + 4*j + 0] = acc[j].x * invT;
            As[bb][kk0 + 4*j + 1] = acc[j].y * invT;
            As[bb][kk0 + 4*j + 2] = acc[j].z * invT;
            As[bb][kk0 + 4*j + 3] = acc[j].w * invT;
        }
    }
    {   // load W 64x128
        int e = tid >> 2;
        int kk0 = (tid & 3) * 32;
        const float* src = W + (size_t)(e0 + e) * D_ + k0 + kk0;
        #pragma unroll
        for (int j = 0; j < 32; j++) Ws[e][kk0 + j] = src[j];
    }
    __syncthreads();
    int tb = tid & 15, te = tid >> 4;
    float accA[4] = {0,0,0,0}, accB[4] = {0,0,0,0};
    #pragma unroll 4
    for (int k = 0; k < 128; k++) {
        float a0 = As[tb][k], a1 = As[tb + 16][k];
        #pragma unroll
        for (int i = 0; i < 4; i++) {
            float w = Ws[te * 4 + i][k];
            accA[i] += a0 * w;
            accB[i] += a1 * w;
        }
    }
    #pragma unroll
    for (int i = 0; i < 4; i++) {
        g_pxp[((size_t)ks * B_ + tb     ) * D_ + e0 + te * 4 + i] = accA[i];
        g_pxp[((size_t)ks * B_ + tb + 16) * D_ + e0 + te * 4 + i] = accB[i];
    }
}

// ---------------- KC: MLP split-K GEMM, xp reduce+bias fused into A-load ----------------
// h_pre[b,j] = sum_d xp[b,d]*W1[j,d];  grid (8 e-tiles of 64, 16 k-splits of 64)
__global__ __launch_bounds__(256) void kC_gemm_mlp(const float* __restrict__ W1,
                                                   const float* __restrict__ xa_b) {
    __shared__ float As[B_][65];
    __shared__ float Ws[64][65];
    int et = blockIdx.x, ks = blockIdx.y;
    int e0 = et * 64, k0 = ks * 64;
    int tid = threadIdx.x;
    {   // load A 32x64, reducing 8 xp k-split partials, + bias
        int bb  = tid >> 3;          // 0..31
        int kk0 = (tid & 7) * 8;     // 2 float4 per thread
        float4 acc[2] = {{0,0,0,0},{0,0,0,0}};
        #pragma unroll
        for (int s = 0; s < 8; s++) {
            const float4* src = (const float4*)(g_pxp + ((size_t)s * B_ + bb) * D_ + k0 + kk0);
            #pragma unroll
            for (int j = 0; j < 2; j++) {
                float4 v = src[j];
                acc[j].x += v.x; acc[j].y += v.y; acc[j].z += v.z; acc[j].w += v.w;
            }
        }
        const float4* bv = (const float4*)(xa_b + k0 + kk0);
        #pragma unroll
        for (int j = 0; j < 2; j++) {
            float4 bb4 = bv[j];
            As[bb][kk0 + 4*j + 0] = acc[j].x + bb4.x;
            As[bb][kk0 + 4*j + 1] = acc[j].y + bb4.y;
            As[bb][kk0 + 4*j + 2] = acc[j].z + bb4.z;
            As[bb][kk0 + 4*j + 3] = acc[j].w + bb4.w;
        }
    }
    {   // load W1 64x64
        int e = tid >> 2;
        int kk0 = (tid & 3) * 16;
        const float* src = W1 + (size_t)(e0 + e) * D_ + k0 + kk0;
        #pragma unroll
        for (int j = 0; j < 16; j++) Ws[e][kk0 + j] = src[j];
    }
    __syncthreads();
    int tb = tid & 15, te = tid >> 4;
    float accA[4] = {0,0,0,0}, accB[4] = {0,0,0,0};
    #pragma unroll 4
    for (int k = 0; k < 64; k++) {
        float a0 = As[tb][k], a1 = As[tb + 16][k];
        #pragma unroll
        for (int i = 0; i < 4; i++) {
            float w = Ws[te * 4 + i][k];
            accA[i] += a0 * w;
            accB[i] += a1 * w;
        }
    }
    #pragma unroll
    for (int i = 0; i < 4; i++) {
        g_ph[((size_t)ks * B_ + tb     ) * HID_ + e0 + te * 4 + i] = accA[i];
        g_ph[((size_t)ks * B_ + tb + 16) * HID_ + e0 + te * 4 + i] = accB[i];
    }
}

// ---------------- block reduce helper ----------------
__device__ __forceinline__ float blockReduce(float v, volatile float* rbuf) {
    unsigned m = 0xffffffffu;
    v += __shfl_down_sync(m, v, 16);
    v += __shfl_down_sync(m, v, 8);
    v += __shfl_down_sync(m, v, 4);
    v += __shfl_down_sync(m, v, 2);
    v += __shfl_down_sync(m, v, 1);
    __syncthreads();
    if ((threadIdx.x & 31) == 0) rbuf[threadIdx.x >> 5] = v;
    __syncthreads();
    float s = rbuf[0];
    #pragma unroll
    for (int i = 1; i < 8; i++) s += rbuf[i];
    return s;
}

// reduce one xp row from partials + bias (identical order everywhere -> bit-identical)
__device__ __forceinline__ float4 xp_reduce4(int b, int tid, const float4* xab4) {
    float4 v = {0,0,0,0};
    #pragma unroll
    for (int s = 0; s < 8; s++) {
        float4 t = ((const float4*)(g_pxp + ((size_t)s * B_ + b) * D_))[tid];
        v.x += t.x; v.y += t.y; v.z += t.z; v.w += t.w;
    }
    float4 bb = xab4[tid];
    v.x += bb.x; v.y += bb.y; v.z += bb.z; v.w += bb.w;
    return v;
}

// ---------------- KD: fully fused tail (per batch block) ----------------
// grid 32 blocks x 256 threads; each block writes out[b] and out[32+b]
__global__ __launch_bounds__(256) void kD_tail(
    const float* __restrict__ mkey0, const float* __restrict__ mkey1,
    const float* __restrict__ keym,  const float* __restrict__ valm,
    const float* __restrict__ w2,    const float* __restrict__ b2,
    const float* __restrict__ cw,    const float* __restrict__ cb,
    const float* __restrict__ xa_b,  const float* __restrict__ mlp_b1,
    const float* __restrict__ thr,   float* __restrict__ out) {
    int b = blockIdx.x;
    int tid = threadIdx.x;
    int lane = tid & 31;
    __shared__ float xps[D_];
    __shared__ float rbuf[8];
    __shared__ float logits[MEM_];

    const float4* xab4 = (const float4*)xa_b;
    float4 v = xp_reduce4(b, tid, xab4);
    ((float4*)xps)[tid] = v;

    float4 pv = {0,0,0,0};
    if (b > 0) pv = xp_reduce4(b - 1, tid, xab4);

    float4 m0 = ((const float4*)mkey0)[tid];
    float4 m1 = ((const float4*)mkey1)[tid];

    float xsq = v.x*v.x + v.y*v.y + v.z*v.z + v.w*v.w;
    float d0  = v.x*m0.x + v.y*m0.y + v.z*m0.z + v.w*m0.w;
    float d1  = v.x*m1.x + v.y*m1.y + v.z*m1.z + v.w*m1.w;
    float n0  = m0.x*m0.x + m0.y*m0.y + m0.z*m0.z + m0.w*m0.w;
    float n1  = m1.x*m1.x + m1.y*m1.y + m1.z*m1.z + m1.w*m1.w;
    float psq = pv.x*pv.x + pv.y*pv.y + pv.z*pv.z + pv.w*pv.w;
    float pd0 = pv.x*m0.x + pv.y*m0.y + pv.z*m0.z + pv.w*m0.w;
    float pd1 = pv.x*m1.x + pv.y*m1.y + pv.z*m1.z + pv.w*m1.w;

    xsq = blockReduce(xsq, rbuf);
    d0  = blockReduce(d0,  rbuf);
    d1  = blockReduce(d1,  rbuf);
    n0  = blockReduce(n0,  rbuf);
    n1  = blockReduce(n1,  rbuf);
    psq = blockReduce(psq, rbuf);
    pd0 = blockReduce(pd0, rbuf);
    pd1 = blockReduce(pd1, rbuf);
    // xps fully visible now (barriers inside reduces)

    float nx = sqrtf(xsq);
    float sn0 = sqrtf(n0), sn1 = sqrtf(n1);
    float s0 = d0 / fmaxf(nx * sn0, 1e-8f);
    float s1 = d1 / fmaxf(nx * sn1, 1e-8f);
    int best = (s1 > s0) ? 1 : 0;
    float changed = 1.0f;
    if (b > 0) {
        float pn  = sqrtf(psq);
        float ps0 = pd0 / fmaxf(pn * sn0, 1e-8f);
        float ps1 = pd1 / fmaxf(pn * sn1, 1e-8f);
        int pbest = (ps1 > ps0) ? 1 : 0;
        changed = (best != pbest) ? 1.0f : 0.0f;
    }

    // attention logits: warp w handles keys w*8..w*8+7
    float inv_nx = 1.0f / fmaxf(nx, 1e-12f);
    int w = tid >> 5;
    #pragma unroll
    for (int q = 0; q < 8; q++) {
        int mrow = w * 8 + q;
        const float* kr = keym + mrow * D_;
        float dot = 0.f, ksq = 0.f;
        #pragma unroll 4
        for (int j = lane; j < D_; j += 32) {
            float kv = kr[j];
            dot += kv * xps[j];
            ksq += kv * kv;
        }
        #pragma unroll
        for (int o = 16; o > 0; o >>= 1) {
            dot += __shfl_down_sync(0xffffffffu, dot, o);
            ksq += __shfl_down_sync(0xffffffffu, ksq, o);
        }
        if (lane == 0) {
            float nk = sqrtf(ksq);
            logits[mrow] = dot * inv_nx / fmaxf(nk, 1e-12f) * (1.0f / 32.0f);
        }
    }

    // h reduce (16 partials) + bias + silu + dot(w2); its blockReduce barriers
    // also order logits[] writes before the softmax below.
    float2 hv = {0.f, 0.f};
    #pragma unroll
    for (int s = 0; s < 16; s++) {
        float2 t = ((const float2*)(g_ph + ((size_t)s * B_ + b) * HID_))[tid];
        hv.x += t.x; hv.y += t.y;
    }
    hv.x += mlp_b1[2*tid];
    hv.y += mlp_b1[2*tid + 1];
    float h0 = hv.x / (1.0f + expf(-hv.x));
    float h1 = hv.y / (1.0f + expf(-hv.y));
    float mp = h0 * w2[2*tid] + h1 * w2[2*tid + 1];
    float mlp_out = blockReduce(mp, rbuf) + b2[0];

    // warp 0: softmax over 64 logits + value dot; write outputs
    if (tid < 32) {
        float l0 = logits[tid], l1 = logits[tid + 32];
        float mx = fmaxf(l0, l1);
        #pragma unroll
        for (int o = 16; o > 0; o >>= 1) mx = fmaxf(mx, __shfl_xor_sync(0xffffffffu, mx, o));
        float e0 = expf(l0 - mx), e1 = expf(l1 - mx);
        float ssum = e0 + e1;
        float vsum = e0 * valm[tid] + e1 * valm[tid + 32];
        #pragma unroll
        for (int o = 16; o > 0; o >>= 1) {
            ssum += __shfl_down_sync(0xffffffffu, ssum, o);
            vsum += __shfl_down_sync(0xffffffffu, vsum, o);
        }
        if (tid == 0) {
            float mem_val = vsum / ssum;
            out[b]      = (changed > thr[0]) ? 1.0f : 0.0f;
            out[B_ + b] = cw[0] * mem_val + cw[1] * mlp_out + cb[0];
        }
    }
}

// ---------------- launch ----------------
extern "C" void kernel_launch(void* const* d_in, const int* in_sizes, int n_in,
                              void* d_out, int out_size) {
    const float* x       = (const float*)d_in[0];
    const float* mkey0   = (const float*)d_in[1];
    const float* mkey1   = (const float*)d_in[2];
    const float* keym    = (const float*)d_in[3];
    const float* valm    = (const float*)d_in[4];
    const float* mlp_w1  = (const float*)d_in[5];
    const float* mlp_b1  = (const float*)d_in[6];
    const float* mlp_w2  = (const float*)d_in[7];
    const float* mlp_b2  = (const float*)d_in[8];
    const float* cw      = (const float*)d_in[9];
    const float* cb      = (const float*)d_in[10];
    const float* xa_w    = (const float*)d_in[11];
    const float* xa_b    = (const float*)d_in[12];
    const float* thr     = (const float*)d_in[13];
    float* out = (float*)d_out;

    kA_mean<<<dim3(TS_, 32), 256>>>(x);
    kB_gemm_xp<<<dim3(16, 8), 256>>>(xa_w);
    kC_gemm_mlp<<<dim3(8, 16), 256>>>(mlp_w1, xa_b);
    kD_tail<<<32, 256>>>(mkey0, mkey1, keym, valm, mlp_w2, mlp_b2,
                         cw, cb, xa_b, mlp_b1, thr, out);
}

// round 4
// speedup vs baseline: 1.2958x; 1.2958x over previous
#include <cuda_runtime.h>
#include <cuda_bf16.h>
#include <math.h>

#define B_   32
#define T_   2048
#define D_   1024
#define MEM_ 64
#define HID_ 512   // D/2
#define TS_  8     // time splits in mean kernel

// ---------------- device scratch (no allocations allowed) ----------------
__device__ __align__(16) float g_part[TS_ * B_ * D_];  // mean partials [ts][b][d]
__device__ __align__(16) float g_pxp [8 * B_ * D_];    // xp partials   [ks][b][e]
__device__ __align__(16) float g_ph  [16 * B_ * HID_]; // h partials    [ks][b][j]

// ---------------- KA: mean over T, partial sums ----------------
// grid (8 tsplits, 32 batches), 256 threads; thread owns 4 d-cols (float4),
// 8 independent streaming loads + 8 accumulator chains in flight.
__global__ __launch_bounds__(256) void kA_mean(const float* __restrict__ x) {
    int ts = blockIdx.x;   // 0..7
    int b  = blockIdx.y;   // 0..31
    int tid = threadIdx.x;
    const float4* p = (const float4*)(x + ((size_t)b * T_ + (size_t)ts * 256) * D_) + tid;
    float4 a0 = {0,0,0,0}, a1 = a0, a2 = a0, a3 = a0, a4 = a0, a5 = a0, a6 = a0, a7 = a0;
    for (int t = 0; t < 256; t += 8) {
        float4 v0 = __ldcs(&p[(t + 0) * (D_/4)]);
        float4 v1 = __ldcs(&p[(t + 1) * (D_/4)]);
        float4 v2 = __ldcs(&p[(t + 2) * (D_/4)]);
        float4 v3 = __ldcs(&p[(t + 3) * (D_/4)]);
        float4 v4 = __ldcs(&p[(t + 4) * (D_/4)]);
        float4 v5 = __ldcs(&p[(t + 5) * (D_/4)]);
        float4 v6 = __ldcs(&p[(t + 6) * (D_/4)]);
        float4 v7 = __ldcs(&p[(t + 7) * (D_/4)]);
        a0.x += v0.x; a0.y += v0.y; a0.z += v0.z; a0.w += v0.w;
        a1.x += v1.x; a1.y += v1.y; a1.z += v1.z; a1.w += v1.w;
        a2.x += v2.x; a2.y += v2.y; a2.z += v2.z; a2.w += v2.w;
        a3.x += v3.x; a3.y += v3.y; a3.z += v3.z; a3.w += v3.w;
        a4.x += v4.x; a4.y += v4.y; a4.z += v4.z; a4.w += v4.w;
        a5.x += v5.x; a5.y += v5.y; a5.z += v5.z; a5.w += v5.w;
        a6.x += v6.x; a6.y += v6.y; a6.z += v6.z; a6.w += v6.w;
        a7.x += v7.x; a7.y += v7.y; a7.z += v7.z; a7.w += v7.w;
    }
    float4 s;
    s.x = ((a0.x + a1.x) + (a2.x + a3.x)) + ((a4.x + a5.x) + (a6.x + a7.x));
    s.y = ((a0.y + a1.y) + (a2.y + a3.y)) + ((a4.y + a5.y) + (a6.y + a7.y));
    s.z = ((a0.z + a1.z) + (a2.z + a3.z)) + ((a4.z + a5.z) + (a6.z + a7.z));
    s.w = ((a0.w + a1.w) + (a2.w + a3.w)) + ((a4.w + a5.w) + (a6.w + a7.w));
    ((float4*)g_part)[(ts * B_ + b) * (D_/4) + tid] = s;
}

// ---------------- KB: xp split-K GEMM, mean-finalize fused into A-load ----------------
__global__ __launch_bounds__(256) void kB_gemm_xp(const float* __restrict__ W) {
    __shared__ float As[B_][129];
    __shared__ float Ws[64][129];
    int et = blockIdx.x, ks = blockIdx.y;
    int e0 = et * 64, k0 = ks * 128;
    int tid = threadIdx.x;
    {   // load A 32x128, reducing 8 time-partials, * 1/T
        int bb  = tid >> 3;
        int kk0 = (tid & 7) * 16;
        float4 acc[4] = {{0,0,0,0},{0,0,0,0},{0,0,0,0},{0,0,0,0}};
        #pragma unroll
        for (int ts = 0; ts < TS_; ts++) {
            const float4* src = (const float4*)(g_part + ((size_t)ts * B_ + bb) * D_ + k0 + kk0);
            #pragma unroll
            for (int j = 0; j < 4; j++) {
                float4 v = src[j];
                acc[j].x += v.x; acc[j].y += v.y; acc[j].z += v.z; acc[j].w += v.w;
            }
        }
        const float invT = 1.0f / (float)T_;
        #pragma unroll
        for (int j = 0; j < 4; j++) {
            As[bb][kk0 + 4*j + 0] = acc[j].x * invT;
            As[bb][kk0 + 4*j + 1] = acc[j].y * invT;
            As[bb][kk0 + 4*j + 2] = acc[j].z * invT;
            As[bb][kk0 + 4*j + 3] = acc[j].w * invT;
        }
    }
    {   // load W 64x128
        int e = tid >> 2;
        int kk0 = (tid & 3) * 32;
        const float* src = W + (size_t)(e0 + e) * D_ + k0 + kk0;
        #pragma unroll
        for (int j = 0; j < 32; j++) Ws[e][kk0 + j] = src[j];
    }
    __syncthreads();
    int tb = tid & 15, te = tid >> 4;
    float accA[4] = {0,0,0,0}, accB[4] = {0,0,0,0};
    #pragma unroll 4
    for (int k = 0; k < 128; k++) {
        float a0 = As[tb][k], a1 = As[tb + 16][k];
        #pragma unroll
        for (int i = 0; i < 4; i++) {
            float w = Ws[te * 4 + i][k];
            accA[i] += a0 * w;
            accB[i] += a1 * w;
        }
    }
    #pragma unroll
    for (int i = 0; i < 4; i++) {
        g_pxp[((size_t)ks * B_ + tb     ) * D_ + e0 + te * 4 + i] = accA[i];
        g_pxp[((size_t)ks * B_ + tb + 16) * D_ + e0 + te * 4 + i] = accB[i];
    }
}

// ---------------- KC: MLP split-K GEMM, xp reduce+bias fused into A-load ----------------
__global__ __launch_bounds__(256) void kC_gemm_mlp(const float* __restrict__ W1,
                                                   const float* __restrict__ xa_b) {
    __shared__ float As[B_][65];
    __shared__ float Ws[64][65];
    int et = blockIdx.x, ks = blockIdx.y;
    int e0 = et * 64, k0 = ks * 64;
    int tid = threadIdx.x;
    {   // load A 32x64, reducing 8 xp k-split partials, + bias
        int bb  = tid >> 3;
        int kk0 = (tid & 7) * 8;
        float4 acc[2] = {{0,0,0,0},{0,0,0,0}};
        #pragma unroll
        for (int s = 0; s < 8; s++) {
            const float4* src = (const float4*)(g_pxp + ((size_t)s * B_ + bb) * D_ + k0 + kk0);
            #pragma unroll
            for (int j = 0; j < 2; j++) {
                float4 v = src[j];
                acc[j].x += v.x; acc[j].y += v.y; acc[j].z += v.z; acc[j].w += v.w;
            }
        }
        const float4* bv = (const float4*)(xa_b + k0 + kk0);
        #pragma unroll
        for (int j = 0; j < 2; j++) {
            float4 bb4 = bv[j];
            As[bb][kk0 + 4*j + 0] = acc[j].x + bb4.x;
            As[bb][kk0 + 4*j + 1] = acc[j].y + bb4.y;
            As[bb][kk0 + 4*j + 2] = acc[j].z + bb4.z;
            As[bb][kk0 + 4*j + 3] = acc[j].w + bb4.w;
        }
    }
    {   // load W1 64x64
        int e = tid >> 2;
        int kk0 = (tid & 3) * 16;
        const float* src = W1 + (size_t)(e0 + e) * D_ + k0 + kk0;
        #pragma unroll
        for (int j = 0; j < 16; j++) Ws[e][kk0 + j] = src[j];
    }
    __syncthreads();
    int tb = tid & 15, te = tid >> 4;
    float accA[4] = {0,0,0,0}, accB[4] = {0,0,0,0};
    #pragma unroll 4
    for (int k = 0; k < 64; k++) {
        float a0 = As[tb][k], a1 = As[tb + 16][k];
        #pragma unroll
        for (int i = 0; i < 4; i++) {
            float w = Ws[te * 4 + i][k];
            accA[i] += a0 * w;
            accB[i] += a1 * w;
        }
    }
    #pragma unroll
    for (int i = 0; i < 4; i++) {
        g_ph[((size_t)ks * B_ + tb     ) * HID_ + e0 + te * 4 + i] = accA[i];
        g_ph[((size_t)ks * B_ + tb + 16) * HID_ + e0 + te * 4 + i] = accB[i];
    }
}

// ---------------- reduce one xp row from partials + bias ----------------
__device__ __forceinline__ float4 xp_reduce4(int b, int tid, const float4* xab4) {
    float4 v = {0,0,0,0};
    #pragma unroll
    for (int s = 0; s < 8; s++) {
        float4 t = ((const float4*)(g_pxp + ((size_t)s * B_ + b) * D_))[tid];
        v.x += t.x; v.y += t.y; v.z += t.z; v.w += t.w;
    }
    float4 bb = xab4[tid];
    v.x += bb.x; v.y += bb.y; v.z += bb.z; v.w += bb.w;
    return v;
}

// ---------------- KD: fully fused tail (per batch block) ----------------
// grid 32 blocks x 256 threads
__global__ __launch_bounds__(256) void kD_tail(
    const float* __restrict__ mkey0, const float* __restrict__ mkey1,
    const float* __restrict__ keym,  const float* __restrict__ valm,
    const float* __restrict__ w2,    const float* __restrict__ b2,
    const float* __restrict__ cw,    const float* __restrict__ cb,
    const float* __restrict__ xa_b,  const float* __restrict__ mlp_b1,
    const float* __restrict__ thr,   float* __restrict__ out) {
    int b = blockIdx.x;
    int tid = threadIdx.x;
    int lane = tid & 31;
    int w = tid >> 5;
    __shared__ __align__(16) float xps[D_];
    __shared__ __align__(16) float kt[64][132];   // key tile 64 x 128 (+4 pad)
    __shared__ float red[8][8];
    __shared__ float rbuf[8];
    __shared__ float logits[MEM_];

    const float4* xab4 = (const float4*)xa_b;
    float4 v = xp_reduce4(b, tid, xab4);
    ((float4*)xps)[tid] = v;

    float4 pv = {0,0,0,0};
    if (b > 0) pv = xp_reduce4(b - 1, tid, xab4);

    float4 m0 = ((const float4*)mkey0)[tid];
    float4 m1 = ((const float4*)mkey1)[tid];

    // 8 packed reductions: xsq,d0,d1,n0,n1,psq,pd0,pd1
    float r8[8];
    r8[0] = v.x*v.x + v.y*v.y + v.z*v.z + v.w*v.w;
    r8[1] = v.x*m0.x + v.y*m0.y + v.z*m0.z + v.w*m0.w;
    r8[2] = v.x*m1.x + v.y*m1.y + v.z*m1.z + v.w*m1.w;
    r8[3] = m0.x*m0.x + m0.y*m0.y + m0.z*m0.z + m0.w*m0.w;
    r8[4] = m1.x*m1.x + m1.y*m1.y + m1.z*m1.z + m1.w*m1.w;
    r8[5] = pv.x*pv.x + pv.y*pv.y + pv.z*pv.z + pv.w*pv.w;
    r8[6] = pv.x*m0.x + pv.y*m0.y + pv.z*m0.z + pv.w*m0.w;
    r8[7] = pv.x*m1.x + pv.y*m1.y + pv.z*m1.z + pv.w*m1.w;
    #pragma unroll
    for (int o = 16; o > 0; o >>= 1) {
        #pragma unroll
        for (int i = 0; i < 8; i++) r8[i] += __shfl_down_sync(0xffffffffu, r8[i], o);
    }
    if (lane == 0) {
        #pragma unroll
        for (int i = 0; i < 8; i++) red[w][i] = r8[i];
    }
    __syncthreads();   // also publishes xps[]
    float sums[8];
    #pragma unroll
    for (int i = 0; i < 8; i++) {
        float s = red[0][i];
        #pragma unroll
        for (int ww = 1; ww < 8; ww++) s += red[ww][i];
        sums[i] = s;
    }

    float nx  = sqrtf(sums[0]);
    float sn0 = sqrtf(sums[3]), sn1 = sqrtf(sums[4]);
    float s0 = sums[1] / fmaxf(nx * sn0, 1e-8f);
    float s1 = sums[2] / fmaxf(nx * sn1, 1e-8f);
    int best = (s1 > s0) ? 1 : 0;
    float changed = 1.0f;
    if (b > 0) {
        float pn  = sqrtf(sums[5]);
        float ps0 = sums[6] / fmaxf(pn * sn0, 1e-8f);
        float ps1 = sums[7] / fmaxf(pn * sn1, 1e-8f);
        int pbest = (ps1 > ps0) ? 1 : 0;
        changed = (best != pbest) ? 1.0f : 0.0f;
    }

    // ---- attention: smem-tiled. 8 chunks of 128 d-cols; warp w owns keys w*8..w*8+7
    float dotq[8] = {0,0,0,0,0,0,0,0};
    float ksqq[8] = {0,0,0,0,0,0,0,0};
    for (int c = 0; c < 8; c++) {
        // cooperative tile load: 2048 float4, 8 per thread; warp covers one row per i
        #pragma unroll
        for (int i = 0; i < 8; i++) {
            int f   = tid + i * 256;
            int row = f >> 5;          // 0..63
            int col = f & 31;          // 0..31 (float4 index)
            float4 kv = ((const float4*)(keym + (size_t)row * D_ + c * 128))[col];
            *(float4*)&kt[row][col * 4] = kv;
        }
        __syncthreads();
        float4 xq = ((const float4*)xps)[c * 32 + lane];
        #pragma unroll
        for (int q = 0; q < 8; q++) {
            float4 kq = *(const float4*)&kt[w * 8 + q][lane * 4];
            dotq[q] += kq.x*xq.x + kq.y*xq.y + kq.z*xq.z + kq.w*xq.w;
            ksqq[q] += kq.x*kq.x + kq.y*kq.y + kq.z*kq.z + kq.w*kq.w;
        }
        __syncthreads();
    }
    // per-key lane reduce
    #pragma unroll
    for (int o = 16; o > 0; o >>= 1) {
        #pragma unroll
        for (int q = 0; q < 8; q++) {
            dotq[q] += __shfl_down_sync(0xffffffffu, dotq[q], o);
            ksqq[q] += __shfl_down_sync(0xffffffffu, ksqq[q], o);
        }
    }
    float inv_nx = 1.0f / fmaxf(nx, 1e-12f);
    if (lane == 0) {
        #pragma unroll
        for (int q = 0; q < 8; q++) {
            float nk = sqrtf(ksqq[q]);
            logits[w * 8 + q] = dotq[q] * inv_nx / fmaxf(nk, 1e-12f) * (1.0f / 32.0f);
        }
    }

    // ---- h reduce (16 partials) + bias + silu + dot(w2) ----
    float2 hv = {0.f, 0.f};
    #pragma unroll
    for (int s = 0; s < 16; s++) {
        float2 t = ((const float2*)(g_ph + ((size_t)s * B_ + b) * HID_))[tid];
        hv.x += t.x; hv.y += t.y;
    }
    float2 b1v = ((const float2*)mlp_b1)[tid];
    float2 w2v = ((const float2*)w2)[tid];
    hv.x += b1v.x; hv.y += b1v.y;
    float h0 = hv.x / (1.0f + expf(-hv.x));
    float h1 = hv.y / (1.0f + expf(-hv.y));
    float mp = h0 * w2v.x + h1 * w2v.y;
    // block reduce mp (barriers also order logits[] before softmax below)
    #pragma unroll
    for (int o = 16; o > 0; o >>= 1) mp += __shfl_down_sync(0xffffffffu, mp, o);
    __syncthreads();
    if (lane == 0) rbuf[w] = mp;
    __syncthreads();
    float mlp_out = rbuf[0];
    #pragma unroll
    for (int i = 1; i < 8; i++) mlp_out += rbuf[i];
    mlp_out += b2[0];

    // ---- warp 0: softmax over 64 logits + value dot; write outputs ----
    if (tid < 32) {
        float l0 = logits[tid], l1 = logits[tid + 32];
        float mx = fmaxf(l0, l1);
        #pragma unroll
        for (int o = 16; o > 0; o >>= 1) mx = fmaxf(mx, __shfl_xor_sync(0xffffffffu, mx, o));
        float e0 = expf(l0 - mx), e1 = expf(l1 - mx);
        float ssum = e0 + e1;
        float vsum = e0 * valm[tid] + e1 * valm[tid + 32];
        #pragma unroll
        for (int o = 16; o > 0; o >>= 1) {
            ssum += __shfl_down_sync(0xffffffffu, ssum, o);
            vsum += __shfl_down_sync(0xffffffffu, vsum, o);
        }
        if (tid == 0) {
            float mem_val = vsum / ssum;
            out[b]      = (changed > thr[0]) ? 1.0f : 0.0f;
            out[B_ + b] = cw[0] * mem_val + cw[1] * mlp_out + cb[0];
        }
    }
}

// ---------------- launch ----------------
extern "C" void kernel_launch(void* const* d_in, const int* in_sizes, int n_in,
                              void* d_out, int out_size) {
    const float* x       = (const float*)d_in[0];
    const float* mkey0   = (const float*)d_in[1];
    const float* mkey1   = (const float*)d_in[2];
    const float* keym    = (const float*)d_in[3];
    const float* valm    = (const float*)d_in[4];
    const float* mlp_w1  = (const float*)d_in[5];
    const float* mlp_b1  = (const float*)d_in[6];
    const float* mlp_w2  = (const float*)d_in[7];
    const float* mlp_b2  = (const float*)d_in[8];
    const float* cw      = (const float*)d_in[9];
    const float* cb      = (const float*)d_in[10];
    const float* xa_w    = (const float*)d_in[11];
    const float* xa_b    = (const float*)d_in[12];
    const float* thr     = (const float*)d_in[13];
    float* out = (float*)d_out;

    kA_mean<<<dim3(TS_, 32), 256>>>(x);
    kB_gemm_xp<<<dim3(16, 8), 256>>>(xa_w);
    kC_gemm_mlp<<<dim3(8, 16), 256>>>(mlp_w1, xa_b);
    kD_tail<<<32, 256>>>(mkey0, mkey1, keym, valm, mlp_w2, mlp_b2,
                         cw, cb, xa_b, mlp_b1, thr, out);
}

// round 5
// speedup vs baseline: 1.4165x; 1.0931x over previous
#include <cuda_runtime.h>
#include <cuda_bf16.h>
#include <math.h>

#define B_   32
#define T_   2048
#define D_   1024
#define MEM_ 64
#define HID_ 512   // D/2
#define TS_  8     // time splits in mean kernel

// ---------------- device scratch (no allocations allowed) ----------------
__device__ __align__(16) float g_part[TS_ * B_ * D_];  // mean partials [ts][b][d]
__device__ __align__(16) float g_pxp [8 * B_ * D_];    // xp partials   [ks][b][e]
__device__ __align__(16) float g_ph  [16 * B_ * HID_]; // h partials    [ks][b][j]

// ---------------- KA: mean over T, partial sums ----------------
// grid (8 tsplits, 32 batches), 256 threads; thread owns 4 d-cols (float4),
// 8 independent streaming loads + 8 accumulator chains in flight.
__global__ __launch_bounds__(256) void kA_mean(const float* __restrict__ x) {
    int ts = blockIdx.x;   // 0..7
    int b  = blockIdx.y;   // 0..31
    int tid = threadIdx.x;
    const float4* p = (const float4*)(x + ((size_t)b * T_ + (size_t)ts * 256) * D_) + tid;
    float4 a0 = {0,0,0,0}, a1 = a0, a2 = a0, a3 = a0, a4 = a0, a5 = a0, a6 = a0, a7 = a0;
    for (int t = 0; t < 256; t += 8) {
        float4 v0 = __ldcs(&p[(t + 0) * (D_/4)]);
        float4 v1 = __ldcs(&p[(t + 1) * (D_/4)]);
        float4 v2 = __ldcs(&p[(t + 2) * (D_/4)]);
        float4 v3 = __ldcs(&p[(t + 3) * (D_/4)]);
        float4 v4 = __ldcs(&p[(t + 4) * (D_/4)]);
        float4 v5 = __ldcs(&p[(t + 5) * (D_/4)]);
        float4 v6 = __ldcs(&p[(t + 6) * (D_/4)]);
        float4 v7 = __ldcs(&p[(t + 7) * (D_/4)]);
        a0.x += v0.x; a0.y += v0.y; a0.z += v0.z; a0.w += v0.w;
        a1.x += v1.x; a1.y += v1.y; a1.z += v1.z; a1.w += v1.w;
        a2.x += v2.x; a2.y += v2.y; a2.z += v2.z; a2.w += v2.w;
        a3.x += v3.x; a3.y += v3.y; a3.z += v3.z; a3.w += v3.w;
        a4.x += v4.x; a4.y += v4.y; a4.z += v4.z; a4.w += v4.w;
        a5.x += v5.x; a5.y += v5.y; a5.z += v5.z; a5.w += v5.w;
        a6.x += v6.x; a6.y += v6.y; a6.z += v6.z; a6.w += v6.w;
        a7.x += v7.x; a7.y += v7.y; a7.z += v7.z; a7.w += v7.w;
    }
    float4 s;
    s.x = ((a0.x + a1.x) + (a2.x + a3.x)) + ((a4.x + a5.x) + (a6.x + a7.x));
    s.y = ((a0.y + a1.y) + (a2.y + a3.y)) + ((a4.y + a5.y) + (a6.y + a7.y));
    s.z = ((a0.z + a1.z) + (a2.z + a3.z)) + ((a4.z + a5.z) + (a6.z + a7.z));
    s.w = ((a0.w + a1.w) + (a2.w + a3.w)) + ((a4.w + a5.w) + (a6.w + a7.w));
    ((float4*)g_part)[(ts * B_ + b) * (D_/4) + tid] = s;
}

// ---------------- KB: xp split-K GEMM, mean-finalize fused into A-load ----------------
__global__ __launch_bounds__(256) void kB_gemm_xp(const float* __restrict__ W) {
    __shared__ float As[B_][129];
    __shared__ __align__(16) float Ws[64][132];   // 132 floats/row: 16B-aligned rows
    int et = blockIdx.x, ks = blockIdx.y;
    int e0 = et * 64, k0 = ks * 128;
    int tid = threadIdx.x;
    {   // load W 64x128, coalesced float4: 4 threads/row, 8 float4 each
        int e = tid >> 2;
        int q = tid & 3;
        const float4* src = (const float4*)(W + (size_t)(e0 + e) * D_ + k0) + q;
        #pragma unroll
        for (int i = 0; i < 8; i++) {
            float4 t = src[i * 4];
            *(float4*)&Ws[e][(q + i * 4) * 4] = t;
        }
    }
    {   // load A 32x128, reducing 8 time-partials, * 1/T
        int bb  = tid >> 3;
        int kk0 = (tid & 7) * 16;
        float4 acc[4] = {{0,0,0,0},{0,0,0,0},{0,0,0,0},{0,0,0,0}};
        #pragma unroll
        for (int ts = 0; ts < TS_; ts++) {
            const float4* src = (const float4*)(g_part + ((size_t)ts * B_ + bb) * D_ + k0 + kk0);
            #pragma unroll
            for (int j = 0; j < 4; j++) {
                float4 v = src[j];
                acc[j].x += v.x; acc[j].y += v.y; acc[j].z += v.z; acc[j].w += v.w;
            }
        }
        const float invT = 1.0f / (float)T_;
        #pragma unroll
        for (int j = 0; j < 4; j++) {
            As[bb][kk0 + 4*j + 0] = acc[j].x * invT;
            As[bb][kk0 + 4*j + 1] = acc[j].y * invT;
            As[bb][kk0 + 4*j + 2] = acc[j].z * invT;
            As[bb][kk0 + 4*j + 3] = acc[j].w * invT;
        }
    }
    __syncthreads();
    int tb = tid & 15, te = tid >> 4;
    float accA[4] = {0,0,0,0}, accB[4] = {0,0,0,0};
    #pragma unroll 4
    for (int k = 0; k < 128; k++) {
        float a0 = As[tb][k], a1 = As[tb + 16][k];
        #pragma unroll
        for (int i = 0; i < 4; i++) {
            float w = Ws[te * 4 + i][k];
            accA[i] += a0 * w;
            accB[i] += a1 * w;
        }
    }
    #pragma unroll
    for (int i = 0; i < 4; i++) {
        g_pxp[((size_t)ks * B_ + tb     ) * D_ + e0 + te * 4 + i] = accA[i];
        g_pxp[((size_t)ks * B_ + tb + 16) * D_ + e0 + te * 4 + i] = accB[i];
    }
}

// ---------------- KC: MLP split-K GEMM, xp reduce+bias fused into A-load ----------------
__global__ __launch_bounds__(256) void kC_gemm_mlp(const float* __restrict__ W1,
                                                   const float* __restrict__ xa_b) {
    __shared__ float As[B_][65];
    __shared__ __align__(16) float Ws[64][68];   // 68 floats/row: 16B-aligned rows
    int et = blockIdx.x, ks = blockIdx.y;
    int e0 = et * 64, k0 = ks * 64;
    int tid = threadIdx.x;
    {   // load W1 64x64, coalesced float4: 4 threads/row, 4 float4 each
        int e = tid >> 2;
        int q = tid & 3;
        const float4* src = (const float4*)(W1 + (size_t)(e0 + e) * D_ + k0) + q;
        #pragma unroll
        for (int i = 0; i < 4; i++) {
            float4 t = src[i * 4];
            *(float4*)&Ws[e][(q + i * 4) * 4] = t;
        }
    }
    {   // load A 32x64, reducing 8 xp k-split partials, + bias
        int bb  = tid >> 3;
        int kk0 = (tid & 7) * 8;
        float4 acc[2] = {{0,0,0,0},{0,0,0,0}};
        #pragma unroll
        for (int s = 0; s < 8; s++) {
            const float4* src = (const float4*)(g_pxp + ((size_t)s * B_ + bb) * D_ + k0 + kk0);
            #pragma unroll
            for (int j = 0; j < 2; j++) {
                float4 v = src[j];
                acc[j].x += v.x; acc[j].y += v.y; acc[j].z += v.z; acc[j].w += v.w;
            }
        }
        const float4* bv = (const float4*)(xa_b + k0 + kk0);
        #pragma unroll
        for (int j = 0; j < 2; j++) {
            float4 bb4 = bv[j];
            As[bb][kk0 + 4*j + 0] = acc[j].x + bb4.x;
            As[bb][kk0 + 4*j + 1] = acc[j].y + bb4.y;
            As[bb][kk0 + 4*j + 2] = acc[j].z + bb4.z;
            As[bb][kk0 + 4*j + 3] = acc[j].w + bb4.w;
        }
    }
    __syncthreads();
    int tb = tid & 15, te = tid >> 4;
    float accA[4] = {0,0,0,0}, accB[4] = {0,0,0,0};
    #pragma unroll 4
    for (int k = 0; k < 64; k++) {
        float a0 = As[tb][k], a1 = As[tb + 16][k];
        #pragma unroll
        for (int i = 0; i < 4; i++) {
            float w = Ws[te * 4 + i][k];
            accA[i] += a0 * w;
            accB[i] += a1 * w;
        }
    }
    #pragma unroll
    for (int i = 0; i < 4; i++) {
        g_ph[((size_t)ks * B_ + tb     ) * HID_ + e0 + te * 4 + i] = accA[i];
        g_ph[((size_t)ks * B_ + tb + 16) * HID_ + e0 + te * 4 + i] = accB[i];
    }
}

// ---------------- reduce one xp row from partials + bias ----------------
__device__ __forceinline__ float4 xp_reduce4(int b, int tid, const float4* xab4) {
    float4 v = {0,0,0,0};
    #pragma unroll
    for (int s = 0; s < 8; s++) {
        float4 t = ((const float4*)(g_pxp + ((size_t)s * B_ + b) * D_))[tid];
        v.x += t.x; v.y += t.y; v.z += t.z; v.w += t.w;
    }
    float4 bb = xab4[tid];
    v.x += bb.x; v.y += bb.y; v.z += bb.z; v.w += bb.w;
    return v;
}

// ---------------- KD: fully fused tail (per batch block) ----------------
// grid 32 blocks x 256 threads
__global__ __launch_bounds__(256) void kD_tail(
    const float* __restrict__ mkey0, const float* __restrict__ mkey1,
    const float* __restrict__ keym,  const float* __restrict__ valm,
    const float* __restrict__ w2,    const float* __restrict__ b2,
    const float* __restrict__ cw,    const float* __restrict__ cb,
    const float* __restrict__ xa_b,  const float* __restrict__ mlp_b1,
    const float* __restrict__ thr,   float* __restrict__ out) {
    int b = blockIdx.x;
    int tid = threadIdx.x;
    int lane = tid & 31;
    int w = tid >> 5;
    __shared__ __align__(16) float xps[D_];
    __shared__ __align__(16) float kt[64][132];   // key tile 64 x 128 (+4 pad)
    __shared__ float red[8][8];
    __shared__ float rbuf[8];
    __shared__ float logits[MEM_];

    // --- prefetch h-partials (consumed after attention; hides their latency) ---
    float2 th[16];
    #pragma unroll
    for (int s = 0; s < 16; s++)
        th[s] = ((const float2*)(g_ph + ((size_t)s * B_ + b) * HID_))[tid];

    const float4* xab4 = (const float4*)xa_b;
    float4 v = xp_reduce4(b, tid, xab4);
    ((float4*)xps)[tid] = v;

    float4 pv = {0,0,0,0};
    if (b > 0) pv = xp_reduce4(b - 1, tid, xab4);

    float4 m0 = ((const float4*)mkey0)[tid];
    float4 m1 = ((const float4*)mkey1)[tid];

    // 8 packed reductions: xsq,d0,d1,n0,n1,psq,pd0,pd1
    float r8[8];
    r8[0] = v.x*v.x + v.y*v.y + v.z*v.z + v.w*v.w;
    r8[1] = v.x*m0.x + v.y*m0.y + v.z*m0.z + v.w*m0.w;
    r8[2] = v.x*m1.x + v.y*m1.y + v.z*m1.z + v.w*m1.w;
    r8[3] = m0.x*m0.x + m0.y*m0.y + m0.z*m0.z + m0.w*m0.w;
    r8[4] = m1.x*m1.x + m1.y*m1.y + m1.z*m1.z + m1.w*m1.w;
    r8[5] = pv.x*pv.x + pv.y*pv.y + pv.z*pv.z + pv.w*pv.w;
    r8[6] = pv.x*m0.x + pv.y*m0.y + pv.z*m0.z + pv.w*m0.w;
    r8[7] = pv.x*m1.x + pv.y*m1.y + pv.z*m1.z + pv.w*m1.w;
    #pragma unroll
    for (int o = 16; o > 0; o >>= 1) {
        #pragma unroll
        for (int i = 0; i < 8; i++) r8[i] += __shfl_down_sync(0xffffffffu, r8[i], o);
    }
    if (lane == 0) {
        #pragma unroll
        for (int i = 0; i < 8; i++) red[w][i] = r8[i];
    }

    // --- prefetch attention chunk 0 while the barrier drains ---
    float4 pre[8];
    #pragma unroll
    for (int i = 0; i < 8; i++) {
        int f = tid + i * 256;
        pre[i] = ((const float4*)(keym + (size_t)(f >> 5) * D_))[f & 31];
    }

    __syncthreads();   // publishes xps[] and red[][]
    float sums[8];
    #pragma unroll
    for (int i = 0; i < 8; i++) {
        float s = red[0][i];
        #pragma unroll
        for (int ww = 1; ww < 8; ww++) s += red[ww][i];
        sums[i] = s;
    }

    float nx  = sqrtf(sums[0]);
    float sn0 = sqrtf(sums[3]), sn1 = sqrtf(sums[4]);
    float s0 = sums[1] / fmaxf(nx * sn0, 1e-8f);
    float s1 = sums[2] / fmaxf(nx * sn1, 1e-8f);
    int best = (s1 > s0) ? 1 : 0;
    float changed = 1.0f;
    if (b > 0) {
        float pn  = sqrtf(sums[5]);
        float ps0 = sums[6] / fmaxf(pn * sn0, 1e-8f);
        float ps1 = sums[7] / fmaxf(pn * sn1, 1e-8f);
        int pbest = (ps1 > ps0) ? 1 : 0;
        changed = (best != pbest) ? 1.0f : 0.0f;
    }

    // ---- attention: smem-tiled + register prefetch pipeline ----
    float dotq[8] = {0,0,0,0,0,0,0,0};
    float ksqq[8] = {0,0,0,0,0,0,0,0};
    for (int c = 0; c < 8; c++) {
        // store prefetched chunk c to smem
        #pragma unroll
        for (int i = 0; i < 8; i++) {
            int f = tid + i * 256;
            *(float4*)&kt[f >> 5][(f & 31) * 4] = pre[i];
        }
        __syncthreads();
        // issue loads for chunk c+1 (latency hidden under compute below)
        if (c < 7) {
            #pragma unroll
            for (int i = 0; i < 8; i++) {
                int f = tid + i * 256;
                pre[i] = ((const float4*)(keym + (size_t)(f >> 5) * D_ + (c + 1) * 128))[f & 31];
            }
        }
        float4 xq = ((const float4*)xps)[c * 32 + lane];
        #pragma unroll
        for (int q = 0; q < 8; q++) {
            float4 kq = *(const float4*)&kt[w * 8 + q][lane * 4];
            dotq[q] += kq.x*xq.x + kq.y*xq.y + kq.z*xq.z + kq.w*xq.w;
            ksqq[q] += kq.x*kq.x + kq.y*kq.y + kq.z*kq.z + kq.w*kq.w;
        }
        __syncthreads();
    }
    // per-key lane reduce
    #pragma unroll
    for (int o = 16; o > 0; o >>= 1) {
        #pragma unroll
        for (int q = 0; q < 8; q++) {
            dotq[q] += __shfl_down_sync(0xffffffffu, dotq[q], o);
            ksqq[q] += __shfl_down_sync(0xffffffffu, ksqq[q], o);
        }
    }
    float inv_nx = 1.0f / fmaxf(nx, 1e-12f);
    if (lane == 0) {
        #pragma unroll
        for (int q = 0; q < 8; q++) {
            float nk = sqrtf(ksqq[q]);
            logits[w * 8 + q] = dotq[q] * inv_nx / fmaxf(nk, 1e-12f) * (1.0f / 32.0f);
        }
    }

    // ---- h: sum prefetched partials + bias + silu + dot(w2) ----
    float2 hv = {0.f, 0.f};
    #pragma unroll
    for (int s = 0; s < 16; s++) { hv.x += th[s].x; hv.y += th[s].y; }
    float2 b1v = ((const float2*)mlp_b1)[tid];
    float2 w2v = ((const float2*)w2)[tid];
    hv.x += b1v.x; hv.y += b1v.y;
    float h0 = hv.x / (1.0f + expf(-hv.x));
    float h1 = hv.y / (1.0f + expf(-hv.y));
    float mp = h0 * w2v.x + h1 * w2v.y;
    #pragma unroll
    for (int o = 16; o > 0; o >>= 1) mp += __shfl_down_sync(0xffffffffu, mp, o);
    __syncthreads();   // also orders logits[] writes before softmax read
    if (lane == 0) rbuf[w] = mp;
    __syncthreads();
    float mlp_out = rbuf[0];
    #pragma unroll
    for (int i = 1; i < 8; i++) mlp_out += rbuf[i];
    mlp_out += b2[0];

    // ---- warp 0: softmax over 64 logits + value dot; write outputs ----
    if (tid < 32) {
        float l0 = logits[tid], l1 = logits[tid + 32];
        float mx = fmaxf(l0, l1);
        #pragma unroll
        for (int o = 16; o > 0; o >>= 1) mx = fmaxf(mx, __shfl_xor_sync(0xffffffffu, mx, o));
        float e0 = expf(l0 - mx), e1 = expf(l1 - mx);
        float ssum = e0 + e1;
        float vsum = e0 * valm[tid] + e1 * valm[tid + 32];
        #pragma unroll
        for (int o = 16; o > 0; o >>= 1) {
            ssum += __shfl_down_sync(0xffffffffu, ssum, o);
            vsum += __shfl_down_sync(0xffffffffu, vsum, o);
        }
        if (tid == 0) {
            float mem_val = vsum / ssum;
            out[b]      = (changed > thr[0]) ? 1.0f : 0.0f;
            out[B_ + b] = cw[0] * mem_val + cw[1] * mlp_out + cb[0];
        }
    }
}

// ---------------- launch ----------------
extern "C" void kernel_launch(void* const* d_in, const int* in_sizes, int n_in,
                              void* d_out, int out_size) {
    const float* x       = (const float*)d_in[0];
    const float* mkey0   = (const float*)d_in[1];
    const float* mkey1   = (const float*)d_in[2];
    const float* keym    = (const float*)d_in[3];
    const float* valm    = (const float*)d_in[4];
    const float* mlp_w1  = (const float*)d_in[5];
    const float* mlp_b1  = (const float*)d_in[6];
    const float* mlp_w2  = (const float*)d_in[7];
    const float* mlp_b2  = (const float*)d_in[8];
    const float* cw      = (const float*)d_in[9];
    const float* cb      = (const float*)d_in[10];
    const float* xa_w    = (const float*)d_in[11];
    const float* xa_b    = (const float*)d_in[12];
    const float* thr     = (const float*)d_in[13];
    float* out = (float*)d_out;

    kA_mean<<<dim3(TS_, 32), 256>>>(x);
    kB_gemm_xp<<<dim3(16, 8), 256>>>(xa_w);
    kC_gemm_mlp<<<dim3(8, 16), 256>>>(mlp_w1, xa_b);
    kD_tail<<<32, 256>>>(mkey0, mkey1, keym, valm, mlp_w2, mlp_b2,
                         cw, cb, xa_b, mlp_b1, thr, out);
}

// round 6
// speedup vs baseline: 1.4968x; 1.0567x over previous
#include <cuda_runtime.h>
#include <cuda_bf16.h>
#include <math.h>

#define B_   32
#define T_   2048
#define D_   1024
#define MEM_ 64
#define HID_ 512   // D/2
#define TS_  8     // time splits in mean kernel

// ---------------- device scratch (no allocations allowed) ----------------
__device__ __align__(16) float g_part[TS_ * B_ * D_];  // mean partials [ts][b][d]
__device__ __align__(16) float g_pxp [8 * B_ * D_];    // xp partials   [ks][b][e]
__device__ __align__(16) float g_ph  [16 * B_ * HID_]; // h partials    [ks][b][j]
__device__ __align__(16) float g_psim[16 * B_ * MEM_]; // sims partials [ks][b][m]
__device__ __align__(16) float g_pksq[16 * MEM_];      // |key|^2 partials [ks][m]
__device__ float g_pxsq[16 * B_];                      // |xp|^2 partials
__device__ float g_pd0 [16 * B_];                      // xp.mkey0 partials
__device__ float g_pd1 [16 * B_];                      // xp.mkey1 partials
__device__ float g_pn0 [16];                           // |mkey0|^2 partials
__device__ float g_pn1 [16];                           // |mkey1|^2 partials

// ---------------- KA: mean over T, partial sums ----------------
__global__ __launch_bounds__(256) void kA_mean(const float* __restrict__ x) {
    int ts = blockIdx.x;   // 0..7
    int b  = blockIdx.y;   // 0..31
    int tid = threadIdx.x;
    const float4* p = (const float4*)(x + ((size_t)b * T_ + (size_t)ts * 256) * D_) + tid;
    float4 a0 = {0,0,0,0}, a1 = a0, a2 = a0, a3 = a0, a4 = a0, a5 = a0, a6 = a0, a7 = a0;
    for (int t = 0; t < 256; t += 8) {
        float4 v0 = __ldcs(&p[(t + 0) * (D_/4)]);
        float4 v1 = __ldcs(&p[(t + 1) * (D_/4)]);
        float4 v2 = __ldcs(&p[(t + 2) * (D_/4)]);
        float4 v3 = __ldcs(&p[(t + 3) * (D_/4)]);
        float4 v4 = __ldcs(&p[(t + 4) * (D_/4)]);
        float4 v5 = __ldcs(&p[(t + 5) * (D_/4)]);
        float4 v6 = __ldcs(&p[(t + 6) * (D_/4)]);
        float4 v7 = __ldcs(&p[(t + 7) * (D_/4)]);
        a0.x += v0.x; a0.y += v0.y; a0.z += v0.z; a0.w += v0.w;
        a1.x += v1.x; a1.y += v1.y; a1.z += v1.z; a1.w += v1.w;
        a2.x += v2.x; a2.y += v2.y; a2.z += v2.z; a2.w += v2.w;
        a3.x += v3.x; a3.y += v3.y; a3.z += v3.z; a3.w += v3.w;
        a4.x += v4.x; a4.y += v4.y; a4.z += v4.z; a4.w += v4.w;
        a5.x += v5.x; a5.y += v5.y; a5.z += v5.z; a5.w += v5.w;
        a6.x += v6.x; a6.y += v6.y; a6.z += v6.z; a6.w += v6.w;
        a7.x += v7.x; a7.y += v7.y; a7.z += v7.z; a7.w += v7.w;
    }
    float4 s;
    s.x = ((a0.x + a1.x) + (a2.x + a3.x)) + ((a4.x + a5.x) + (a6.x + a7.x));
    s.y = ((a0.y + a1.y) + (a2.y + a3.y)) + ((a4.y + a5.y) + (a6.y + a7.y));
    s.z = ((a0.z + a1.z) + (a2.z + a3.z)) + ((a4.z + a5.z) + (a6.z + a7.z));
    s.w = ((a0.w + a1.w) + (a2.w + a3.w)) + ((a4.w + a5.w) + (a6.w + a7.w));
    ((float4*)g_part)[(ts * B_ + b) * (D_/4) + tid] = s;
}

// ---------------- KB: xp split-K GEMM, mean-finalize fused into A-load ----------------
__global__ __launch_bounds__(256) void kB_gemm_xp(const float* __restrict__ W) {
    __shared__ float As[B_][129];
    __shared__ __align__(16) float Ws[64][132];
    int et = blockIdx.x, ks = blockIdx.y;
    int e0 = et * 64, k0 = ks * 128;
    int tid = threadIdx.x;
    {   // load W 64x128, coalesced float4
        int e = tid >> 2;
        int q = tid & 3;
        const float4* src = (const float4*)(W + (size_t)(e0 + e) * D_ + k0) + q;
        #pragma unroll
        for (int i = 0; i < 8; i++) {
            float4 t = src[i * 4];
            *(float4*)&Ws[e][(q + i * 4) * 4] = t;
        }
    }
    {   // load A 32x128, reducing 8 time-partials, * 1/T
        int bb  = tid >> 3;
        int kk0 = (tid & 7) * 16;
        float4 acc[4] = {{0,0,0,0},{0,0,0,0},{0,0,0,0},{0,0,0,0}};
        #pragma unroll
        for (int ts = 0; ts < TS_; ts++) {
            const float4* src = (const float4*)(g_part + ((size_t)ts * B_ + bb) * D_ + k0 + kk0);
            #pragma unroll
            for (int j = 0; j < 4; j++) {
                float4 v = src[j];
                acc[j].x += v.x; acc[j].y += v.y; acc[j].z += v.z; acc[j].w += v.w;
            }
        }
        const float invT = 1.0f / (float)T_;
        #pragma unroll
        for (int j = 0; j < 4; j++) {
            As[bb][kk0 + 4*j + 0] = acc[j].x * invT;
            As[bb][kk0 + 4*j + 1] = acc[j].y * invT;
            As[bb][kk0 + 4*j + 2] = acc[j].z * invT;
            As[bb][kk0 + 4*j + 3] = acc[j].w * invT;
        }
    }
    __syncthreads();
    int tb = tid & 15, te = tid >> 4;
    float accA[4] = {0,0,0,0}, accB[4] = {0,0,0,0};
    #pragma unroll 4
    for (int k = 0; k < 128; k++) {
        float a0 = As[tb][k], a1 = As[tb + 16][k];
        #pragma unroll
        for (int i = 0; i < 4; i++) {
            float w = Ws[te * 4 + i][k];
            accA[i] += a0 * w;
            accB[i] += a1 * w;
        }
    }
    #pragma unroll
    for (int i = 0; i < 4; i++) {
        g_pxp[((size_t)ks * B_ + tb     ) * D_ + e0 + te * 4 + i] = accA[i];
        g_pxp[((size_t)ks * B_ + tb + 16) * D_ + e0 + te * 4 + i] = accB[i];
    }
}

// ---------------- KC: MLP GEMM + attention-logits GEMM, xp reduce fused ----------------
// grid (9 tiles, 16 k-splits): x<8 -> MLP output tile; x==8 -> attention/stats tile
__global__ __launch_bounds__(256) void kC_gemm_mlp(const float* __restrict__ W1,
                                                   const float* __restrict__ xa_b,
                                                   const float* __restrict__ keym,
                                                   const float* __restrict__ mkey0,
                                                   const float* __restrict__ mkey1) {
    __shared__ float As[B_][65];
    __shared__ __align__(16) float Ws[64][68];
    __shared__ float mk0s[64], mk1s[64];
    int et = blockIdx.x, ks = blockIdx.y;
    int k0 = ks * 64;
    int tid = threadIdx.x;
    bool attn = (et == 8);

    {   // load weight tile 64x64, coalesced float4 (W1 tile or keym chunk)
        int e = tid >> 2;
        int q = tid & 3;
        const float* base = attn ? (keym + (size_t)e * D_ + k0)
                                 : (W1 + (size_t)(et * 64 + e) * D_ + k0);
        const float4* src = (const float4*)base + q;
        #pragma unroll
        for (int i = 0; i < 4; i++) {
            float4 t = src[i * 4];
            *(float4*)&Ws[e][(q + i * 4) * 4] = t;
        }
    }
    if (attn && tid >= 192) {   // stage mkey chunks
        int i = tid - 192;      // 0..63
        mk0s[i] = mkey0[k0 + i];
        mk1s[i] = mkey1[k0 + i];
    }
    {   // load A 32x64: reduce 8 xp k-split partials + bias (identical order for all uses)
        int bb  = tid >> 3;
        int kk0 = (tid & 7) * 8;
        float4 acc[2] = {{0,0,0,0},{0,0,0,0}};
        #pragma unroll
        for (int s = 0; s < 8; s++) {
            const float4* src = (const float4*)(g_pxp + ((size_t)s * B_ + bb) * D_ + k0 + kk0);
            #pragma unroll
            for (int j = 0; j < 2; j++) {
                float4 v = src[j];
                acc[j].x += v.x; acc[j].y += v.y; acc[j].z += v.z; acc[j].w += v.w;
            }
        }
        const float4* bv = (const float4*)(xa_b + k0 + kk0);
        #pragma unroll
        for (int j = 0; j < 2; j++) {
            float4 bb4 = bv[j];
            As[bb][kk0 + 4*j + 0] = acc[j].x + bb4.x;
            As[bb][kk0 + 4*j + 1] = acc[j].y + bb4.y;
            As[bb][kk0 + 4*j + 2] = acc[j].z + bb4.z;
            As[bb][kk0 + 4*j + 3] = acc[j].w + bb4.w;
        }
    }
    __syncthreads();
    int tb = tid & 15, te = tid >> 4;
    float accA[4] = {0,0,0,0}, accB[4] = {0,0,0,0};
    #pragma unroll 4
    for (int k = 0; k < 64; k++) {
        float a0 = As[tb][k], a1 = As[tb + 16][k];
        #pragma unroll
        for (int i = 0; i < 4; i++) {
            float w = Ws[te * 4 + i][k];
            accA[i] += a0 * w;
            accB[i] += a1 * w;
        }
    }
    if (!attn) {
        int e0 = et * 64;
        #pragma unroll
        for (int i = 0; i < 4; i++) {
            g_ph[((size_t)ks * B_ + tb     ) * HID_ + e0 + te * 4 + i] = accA[i];
            g_ph[((size_t)ks * B_ + tb + 16) * HID_ + e0 + te * 4 + i] = accB[i];
        }
    } else {
        #pragma unroll
        for (int i = 0; i < 4; i++) {
            g_psim[((size_t)ks * B_ + tb     ) * MEM_ + te * 4 + i] = accA[i];
            g_psim[((size_t)ks * B_ + tb + 16) * MEM_ + te * 4 + i] = accB[i];
        }
        // auxiliary stats for this k-chunk
        if (tid < 64) {            // key sq-norm partial
            float s = 0.f;
            #pragma unroll 8
            for (int k = 0; k < 64; k++) { float w = Ws[tid][k]; s += w * w; }
            g_pksq[ks * MEM_ + tid] = s;
        } else if (tid < 96) {     // xp sq-norm + mkey dot partials
            int bb = tid - 64;
            float sx = 0.f, s0 = 0.f, s1 = 0.f;
            #pragma unroll 8
            for (int k = 0; k < 64; k++) {
                float a = As[bb][k];
                sx += a * a;
                s0 += a * mk0s[k];
                s1 += a * mk1s[k];
            }
            g_pxsq[ks * B_ + bb] = sx;
            g_pd0 [ks * B_ + bb] = s0;
            g_pd1 [ks * B_ + bb] = s1;
        } else if (tid == 96) {    // mkey sq-norm partials
            float s = 0.f;
            #pragma unroll 8
            for (int k = 0; k < 64; k++) s += mk0s[k] * mk0s[k];
            g_pn0[ks] = s;
        } else if (tid == 97) {
            float s = 0.f;
            #pragma unroll 8
            for (int k = 0; k < 64; k++) s += mk1s[k] * mk1s[k];
            g_pn1[ks] = s;
        }
    }
}

// ---------------- KD: lightweight tail (per batch block) ----------------
// grid 32 blocks x 256 threads
__global__ __launch_bounds__(256) void kD_tail(
    const float* __restrict__ valm, const float* __restrict__ w2,
    const float* __restrict__ b2,   const float* __restrict__ cw,
    const float* __restrict__ cb,   const float* __restrict__ mlp_b1,
    const float* __restrict__ thr,  float* __restrict__ out) {
    int b = blockIdx.x;
    int tid = threadIdx.x;
    int lane = tid & 31;
    int w = tid >> 5;
    __shared__ float logits[MEM_];
    __shared__ float sc[8];     // xsq,d0,d1, pxsq,pd0,pd1, n0,n1
    __shared__ float rbuf[8];

    // prefetch h partials (16 float2 per thread), independent loads
    float2 th[16];
    #pragma unroll
    for (int s = 0; s < 16; s++)
        th[s] = ((const float2*)(g_ph + ((size_t)s * B_ + b) * HID_))[tid];

    // sims + key-norm partial sums: thread m (<64) owns key m
    float simsum = 0.f, ksum = 0.f;
    if (tid < MEM_) {
        #pragma unroll
        for (int s = 0; s < 16; s++) simsum += g_psim[((size_t)s * B_ + b) * MEM_ + tid];
        #pragma unroll
        for (int s = 0; s < 16; s++) ksum += g_pksq[s * MEM_ + tid];
    } else if (tid >= 64 && tid < 72) {
        // 8 scalar reductions over 16 k-split partials
        int j = tid - 64;
        float s = 0.f;
        if (j < 3) {
            const float* src = (j == 0) ? g_pxsq : (j == 1) ? g_pd0 : g_pd1;
            #pragma unroll
            for (int k = 0; k < 16; k++) s += src[k * B_ + b];
        } else if (j < 6) {
            if (b > 0) {
                const float* src = (j == 3) ? g_pxsq : (j == 4) ? g_pd0 : g_pd1;
                #pragma unroll
                for (int k = 0; k < 16; k++) s += src[k * B_ + (b - 1)];
            }
        } else {
            const float* src = (j == 6) ? g_pn0 : g_pn1;
            #pragma unroll
            for (int k = 0; k < 16; k++) s += src[k];
        }
        sc[j] = s;
    }
    __syncthreads();

    float nx = sqrtf(sc[0]);
    // logits
    if (tid < MEM_) {
        float nk = sqrtf(ksum);
        logits[tid] = simsum / fmaxf(nx, 1e-12f) / fmaxf(nk, 1e-12f) * (1.0f / 32.0f);
    }

    // h: sum partials + bias + silu + dot(w2)
    float2 b1v = ((const float2*)mlp_b1)[tid];
    float2 w2v = ((const float2*)w2)[tid];
    float2 hv = {0.f, 0.f};
    #pragma unroll
    for (int s = 0; s < 16; s++) { hv.x += th[s].x; hv.y += th[s].y; }
    hv.x += b1v.x; hv.y += b1v.y;
    float h0 = hv.x / (1.0f + expf(-hv.x));
    float h1 = hv.y / (1.0f + expf(-hv.y));
    float mp = h0 * w2v.x + h1 * w2v.y;
    #pragma unroll
    for (int o = 16; o > 0; o >>= 1) mp += __shfl_down_sync(0xffffffffu, mp, o);
    __syncthreads();                    // orders logits[] writes before softmax read
    if (lane == 0) rbuf[w] = mp;
    __syncthreads();
    float mlp_out = rbuf[0];
    #pragma unroll
    for (int i = 1; i < 8; i++) mlp_out += rbuf[i];
    mlp_out += b2[0];

    // change detector (all threads compute; only tid 0 uses)
    float sn0 = sqrtf(sc[6]), sn1 = sqrtf(sc[7]);
    float s0 = sc[1] / fmaxf(nx * sn0, 1e-8f);
    float s1 = sc[2] / fmaxf(nx * sn1, 1e-8f);
    int best = (s1 > s0) ? 1 : 0;
    float changed = 1.0f;
    if (b > 0) {
        float pn  = sqrtf(sc[3]);
        float ps0 = sc[4] / fmaxf(pn * sn0, 1e-8f);
        float ps1 = sc[5] / fmaxf(pn * sn1, 1e-8f);
        int pbest = (ps1 > ps0) ? 1 : 0;
        changed = (best != pbest) ? 1.0f : 0.0f;
    }

    // warp 0: softmax over 64 logits + value dot; write outputs
    if (tid < 32) {
        float l0 = logits[tid], l1 = logits[tid + 32];
        float mx = fmaxf(l0, l1);
        #pragma unroll
        for (int o = 16; o > 0; o >>= 1) mx = fmaxf(mx, __shfl_xor_sync(0xffffffffu, mx, o));
        float e0 = expf(l0 - mx), e1 = expf(l1 - mx);
        float ssum = e0 + e1;
        float vsum = e0 * valm[tid] + e1 * valm[tid + 32];
        #pragma unroll
        for (int o = 16; o > 0; o >>= 1) {
            ssum += __shfl_down_sync(0xffffffffu, ssum, o);
            vsum += __shfl_down_sync(0xffffffffu, vsum, o);
        }
        if (tid == 0) {
            float mem_val = vsum / ssum;
            out[b]      = (changed > thr[0]) ? 1.0f : 0.0f;
            out[B_ + b] = cw[0] * mem_val + cw[1] * mlp_out + cb[0];
        }
    }
}

// ---------------- launch ----------------
extern "C" void kernel_launch(void* const* d_in, const int* in_sizes, int n_in,
                              void* d_out, int out_size) {
    const float* x       = (const float*)d_in[0];
    const float* mkey0   = (const float*)d_in[1];
    const float* mkey1   = (const float*)d_in[2];
    const float* keym    = (const float*)d_in[3];
    const float* valm    = (const float*)d_in[4];
    const float* mlp_w1  = (const float*)d_in[5];
    const float* mlp_b1  = (const float*)d_in[6];
    const float* mlp_w2  = (const float*)d_in[7];
    const float* mlp_b2  = (const float*)d_in[8];
    const float* cw      = (const float*)d_in[9];
    const float* cb      = (const float*)d_in[10];
    const float* xa_w    = (const float*)d_in[11];
    const float* xa_b    = (const float*)d_in[12];
    const float* thr     = (const float*)d_in[13];
    float* out = (float*)d_out;

    kA_mean<<<dim3(TS_, 32), 256>>>(x);
    kB_gemm_xp<<<dim3(16, 8), 256>>>(xa_w);
    kC_gemm_mlp<<<dim3(9, 16), 256>>>(mlp_w1, xa_b, keym, mkey0, mkey1);
    kD_tail<<<32, 256>>>(valm, mlp_w2, mlp_b2, cw, cb, mlp_b1, thr, out);
}

// round 9
// speedup vs baseline: 1.6426x; 1.0973x over previous
#include <cuda_runtime.h>
#include <math.h>

#define B_   32
#define T_   2048
#define D_   1024
#define MEM_ 64
#define HID_ 512   // D/2
#define TS_  8     // time splits in mean phase
#define NB_  296   // 2 blocks/SM x 148 SMs; co-residency guaranteed by __launch_bounds__(256,2)

// ---------------- device scratch (no allocations allowed) ----------------
__device__ __align__(16) float g_part[TS_ * B_ * D_];  // mean partials [ts][b][d]
__device__ __align__(16) float g_pxp [8 * B_ * D_];    // xp partials   [ks][b][e]
__device__ __align__(16) float g_ph  [16 * B_ * HID_]; // h partials    [ks][b][j]
__device__ __align__(16) float g_psim[16 * B_ * MEM_]; // sims partials [ks][b][m]
__device__ __align__(16) float g_pksq[16 * MEM_];      // |key|^2 partials
__device__ float g_pxsq[16 * B_];
__device__ float g_pd0 [16 * B_];
__device__ float g_pd1 [16 * B_];
__device__ float g_pn0 [16];
__device__ float g_pn1 [16];
__device__ unsigned long long g_bar;   // monotonic grid-barrier counter (never reset -> replay safe)

// ---------------- dynamic smem pool layout ----------------
#define SA1_STRIDE 129
#define SW1_OFF    (32 * SA1_STRIDE)              // 4128 floats
#define SW1_STRIDE 132
#define POOL_FLOATS (SW1_OFF + 64 * SW1_STRIDE)   // 12576 floats
#define SMEM_BYTES  (POOL_FLOATS * 4)             // 50304 B
#define SA2_STRIDE 65
#define SW2_OFF    (32 * SA2_STRIDE)              // 2080
#define SW2_STRIDE 68
#define MK0_OFF    (SW2_OFF + 64 * SW2_STRIDE)    // 6432
#define MK1_OFF    (MK0_OFF + 64)                 // 6496

// ---------------- grid barrier: monotonic counter, all NB_ blocks resident ----------------
__device__ __forceinline__ void gridBarrier() {
    __threadfence();
    __syncthreads();
    if (threadIdx.x == 0) {
        unsigned long long a = atomicAdd(&g_bar, 1ULL);
        unsigned long long target = (a / NB_ + 1ULL) * (unsigned long long)NB_;
        volatile unsigned long long* p = &g_bar;
        while (*p < target) { }
        __threadfence();
    }
    __syncthreads();
}

__global__ __launch_bounds__(256, 2) void k_all(
    const float* __restrict__ x,
    const float* __restrict__ mkey0, const float* __restrict__ mkey1,
    const float* __restrict__ keym,  const float* __restrict__ valm,
    const float* __restrict__ W1,    const float* __restrict__ mlp_b1,
    const float* __restrict__ w2,    const float* __restrict__ b2,
    const float* __restrict__ cw,    const float* __restrict__ cb,
    const float* __restrict__ Wxa,   const float* __restrict__ xa_b,
    const float* __restrict__ thr,   float* __restrict__ out) {
    extern __shared__ __align__(16) float pool[];
    int bid = blockIdx.x;
    int tid = threadIdx.x;

    // ===== P1 weight preload (blocks 0..127): latency hides under phase 0 =====
    if (bid < 128) {
        int et = bid >> 3, ks = bid & 7;
        int e = tid >> 2, q = tid & 3;
        const float4* src = (const float4*)(Wxa + (size_t)(et * 64 + e) * D_ + ks * 128) + q;
        #pragma unroll
        for (int i = 0; i < 8; i++) {
            float4 t = src[i * 4];
            *(float4*)&pool[SW1_OFF + e * SW1_STRIDE + (q + i * 4) * 4] = t;
        }
    }

    // ===== Phase 0: mean over T, partial sums (256 tiles) =====
    if (bid < 256) {
        int ts = bid >> 5;   // 0..7
        int b  = bid & 31;
        const float4* p = (const float4*)(x + ((size_t)b * T_ + (size_t)ts * 256) * D_) + tid;
        float4 a0 = {0,0,0,0}, a1 = a0, a2 = a0, a3 = a0, a4 = a0, a5 = a0, a6 = a0, a7 = a0;
        for (int t = 0; t < 256; t += 8) {
            float4 v0 = __ldcs(&p[(t + 0) * (D_/4)]);
            float4 v1 = __ldcs(&p[(t + 1) * (D_/4)]);
            float4 v2 = __ldcs(&p[(t + 2) * (D_/4)]);
            float4 v3 = __ldcs(&p[(t + 3) * (D_/4)]);
            float4 v4 = __ldcs(&p[(t + 4) * (D_/4)]);
            float4 v5 = __ldcs(&p[(t + 5) * (D_/4)]);
            float4 v6 = __ldcs(&p[(t + 6) * (D_/4)]);
            float4 v7 = __ldcs(&p[(t + 7) * (D_/4)]);
            a0.x += v0.x; a0.y += v0.y; a0.z += v0.z; a0.w += v0.w;
            a1.x += v1.x; a1.y += v1.y; a1.z += v1.z; a1.w += v1.w;
            a2.x += v2.x; a2.y += v2.y; a2.z += v2.z; a2.w += v2.w;
            a3.x += v3.x; a3.y += v3.y; a3.z += v3.z; a3.w += v3.w;
            a4.x += v4.x; a4.y += v4.y; a4.z += v4.z; a4.w += v4.w;
            a5.x += v5.x; a5.y += v5.y; a5.z += v5.z; a5.w += v5.w;
            a6.x += v6.x; a6.y += v6.y; a6.z += v6.z; a6.w += v6.w;
            a7.x += v7.x; a7.y += v7.y; a7.z += v7.z; a7.w += v7.w;
        }
        float4 s;
        s.x = ((a0.x + a1.x) + (a2.x + a3.x)) + ((a4.x + a5.x) + (a6.x + a7.x));
        s.y = ((a0.y + a1.y) + (a2.y + a3.y)) + ((a4.y + a5.y) + (a6.y + a7.y));
        s.z = ((a0.z + a1.z) + (a2.z + a3.z)) + ((a4.z + a5.z) + (a6.z + a7.z));
        s.w = ((a0.w + a1.w) + (a2.w + a3.w)) + ((a4.w + a5.w) + (a6.w + a7.w));
        ((float4*)g_part)[(ts * B_ + b) * (D_/4) + tid] = s;
    }

    gridBarrier();

    // ===== Phase 1: xp split-K GEMM (128 tiles; weights already in smem) =====
    if (bid < 128) {
        int et = bid >> 3, ks = bid & 7;
        int e0 = et * 64, k0 = ks * 128;
        {   // A 32x128: reduce 8 time partials * 1/T
            int bb  = tid >> 3;
            int kk0 = (tid & 7) * 16;
            float4 acc[4] = {{0,0,0,0},{0,0,0,0},{0,0,0,0},{0,0,0,0}};
            #pragma unroll
            for (int ts = 0; ts < TS_; ts++) {
                const float4* src = (const float4*)(g_part + ((size_t)ts * B_ + bb) * D_ + k0 + kk0);
                #pragma unroll
                for (int j = 0; j < 4; j++) {
                    float4 v = src[j];
                    acc[j].x += v.x; acc[j].y += v.y; acc[j].z += v.z; acc[j].w += v.w;
                }
            }
            const float invT = 1.0f / (float)T_;
            #pragma unroll
            for (int j = 0; j < 4; j++) {
                pool[bb * SA1_STRIDE + kk0 + 4*j + 0] = acc[j].x * invT;
                pool[bb * SA1_STRIDE + kk0 + 4*j + 1] = acc[j].y * invT;
                pool[bb * SA1_STRIDE + kk0 + 4*j + 2] = acc[j].z * invT;
                pool[bb * SA1_STRIDE + kk0 + 4*j + 3] = acc[j].w * invT;
            }
        }
        __syncthreads();
        int tb = tid & 15, te = tid >> 4;
        float accA[4] = {0,0,0,0}, accB[4] = {0,0,0,0};
        #pragma unroll 4
        for (int k = 0; k < 128; k++) {
            float a0 = pool[tb * SA1_STRIDE + k];
            float a1 = pool[(tb + 16) * SA1_STRIDE + k];
            #pragma unroll
            for (int i = 0; i < 4; i++) {
                float w = pool[SW1_OFF + (te * 4 + i) * SW1_STRIDE + k];
                accA[i] += a0 * w;
                accB[i] += a1 * w;
            }
        }
        #pragma unroll
        for (int i = 0; i < 4; i++) {
            g_pxp[((size_t)ks * B_ + tb     ) * D_ + e0 + te * 4 + i] = accA[i];
            g_pxp[((size_t)ks * B_ + tb + 16) * D_ + e0 + te * 4 + i] = accB[i];
        }
    }

    gridBarrier();

    // ===== Phase 2: MLP GEMM + attention-logits GEMM (144 tiles) =====
    if (bid < 144) {
        int et = bid >> 4, ks = bid & 15;   // et 0..8, ks 0..15
        int k0 = ks * 64;
        bool attn = (et == 8);
        {   // weight tile 64x64 coalesced
            int e = tid >> 2, q = tid & 3;
            const float* base = attn ? (keym + (size_t)e * D_ + k0)
                                     : (W1 + (size_t)(et * 64 + e) * D_ + k0);
            const float4* src = (const float4*)base + q;
            #pragma unroll
            for (int i = 0; i < 4; i++) {
                float4 t = src[i * 4];
                *(float4*)&pool[SW2_OFF + e * SW2_STRIDE + (q + i * 4) * 4] = t;
            }
        }
        if (attn && tid >= 192) {
            int i = tid - 192;
            pool[MK0_OFF + i] = mkey0[k0 + i];
            pool[MK1_OFF + i] = mkey1[k0 + i];
        }
        {   // A 32x64: reduce 8 xp partials + bias (identical order everywhere)
            int bb  = tid >> 3;
            int kk0 = (tid & 7) * 8;
            float4 acc[2] = {{0,0,0,0},{0,0,0,0}};
            #pragma unroll
            for (int s = 0; s < 8; s++) {
                const float4* src = (const float4*)(g_pxp + ((size_t)s * B_ + bb) * D_ + k0 + kk0);
                #pragma unroll
                for (int j = 0; j < 2; j++) {
                    float4 v = src[j];
                    acc[j].x += v.x; acc[j].y += v.y; acc[j].z += v.z; acc[j].w += v.w;
                }
            }
            const float4* bv = (const float4*)(xa_b + k0 + kk0);
            #pragma unroll
            for (int j = 0; j < 2; j++) {
                float4 bb4 = bv[j];
                pool[bb * SA2_STRIDE + kk0 + 4*j + 0] = acc[j].x + bb4.x;
                pool[bb * SA2_STRIDE + kk0 + 4*j + 1] = acc[j].y + bb4.y;
                pool[bb * SA2_STRIDE + kk0 + 4*j + 2] = acc[j].z + bb4.z;
                pool[bb * SA2_STRIDE + kk0 + 4*j + 3] = acc[j].w + bb4.w;
            }
        }
        __syncthreads();
        int tb = tid & 15, te = tid >> 4;
        float accA[4] = {0,0,0,0}, accB[4] = {0,0,0,0};
        #pragma unroll 4
        for (int k = 0; k < 64; k++) {
            float a0 = pool[tb * SA2_STRIDE + k];
            float a1 = pool[(tb + 16) * SA2_STRIDE + k];
            #pragma unroll
            for (int i = 0; i < 4; i++) {
                float w = pool[SW2_OFF + (te * 4 + i) * SW2_STRIDE + k];
                accA[i] += a0 * w;
                accB[i] += a1 * w;
            }
        }
        if (!attn) {
            int e0 = et * 64;
            #pragma unroll
            for (int i = 0; i < 4; i++) {
                g_ph[((size_t)ks * B_ + tb     ) * HID_ + e0 + te * 4 + i] = accA[i];
                g_ph[((size_t)ks * B_ + tb + 16) * HID_ + e0 + te * 4 + i] = accB[i];
            }
        } else {
            #pragma unroll
            for (int i = 0; i < 4; i++) {
                g_psim[((size_t)ks * B_ + tb     ) * MEM_ + te * 4 + i] = accA[i];
                g_psim[((size_t)ks * B_ + tb + 16) * MEM_ + te * 4 + i] = accB[i];
            }
            if (tid < 64) {
                float s = 0.f;
                #pragma unroll 8
                for (int k = 0; k < 64; k++) { float w = pool[SW2_OFF + tid * SW2_STRIDE + k]; s += w * w; }
                g_pksq[ks * MEM_ + tid] = s;
            } else if (tid < 96) {
                int bb = tid - 64;
                float sx = 0.f, s0 = 0.f, s1 = 0.f;
                #pragma unroll 8
                for (int k = 0; k < 64; k++) {
                    float a = pool[bb * SA2_STRIDE + k];
                    sx += a * a;
                    s0 += a * pool[MK0_OFF + k];
                    s1 += a * pool[MK1_OFF + k];
                }
                g_pxsq[ks * B_ + bb] = sx;
                g_pd0 [ks * B_ + bb] = s0;
                g_pd1 [ks * B_ + bb] = s1;
            } else if (tid == 96) {
                float s = 0.f;
                #pragma unroll 8
                for (int k = 0; k < 64; k++) s += pool[MK0_OFF + k] * pool[MK0_OFF + k];
                g_pn0[ks] = s;
            } else if (tid == 97) {
                float s = 0.f;
                #pragma unroll 8
                for (int k = 0; k < 64; k++) s += pool[MK1_OFF + k] * pool[MK1_OFF + k];
                g_pn1[ks] = s;
            }
        }
    }

    gridBarrier();

    // ===== Phase 3: tail (32 tiles, one per batch) =====
    if (bid < B_) {
        int b = bid;
        int lane = tid & 31;
        int w = tid >> 5;
        float* logits = pool;        // [64]
        float* sc     = pool + 64;   // [8]
        float* rbuf   = pool + 72;   // [8]

        float2 th[16];
        #pragma unroll
        for (int s = 0; s < 16; s++)
            th[s] = ((const float2*)(g_ph + ((size_t)s * B_ + b) * HID_))[tid];

        float simsum = 0.f, ksum = 0.f;
        if (tid < MEM_) {
            #pragma unroll
            for (int s = 0; s < 16; s++) simsum += g_psim[((size_t)s * B_ + b) * MEM_ + tid];
            #pragma unroll
            for (int s = 0; s < 16; s++) ksum += g_pksq[s * MEM_ + tid];
        } else if (tid >= 64 && tid < 72) {
            int j = tid - 64;
            float s = 0.f;
            if (j < 3) {
                const float* src = (j == 0) ? g_pxsq : (j == 1) ? g_pd0 : g_pd1;
                #pragma unroll
                for (int k = 0; k < 16; k++) s += src[k * B_ + b];
            } else if (j < 6) {
                if (b > 0) {
                    const float* src = (j == 3) ? g_pxsq : (j == 4) ? g_pd0 : g_pd1;
                    #pragma unroll
                    for (int k = 0; k < 16; k++) s += src[k * B_ + (b - 1)];
                }
            } else {
                const float* src = (j == 6) ? g_pn0 : g_pn1;
                #pragma unroll
                for (int k = 0; k < 16; k++) s += src[k];
            }
            sc[j] = s;
        }
        __syncthreads();

        float nx = sqrtf(sc[0]);
        if (tid < MEM_) {
            float nk = sqrtf(ksum);
            logits[tid] = simsum / fmaxf(nx, 1e-12f) / fmaxf(nk, 1e-12f) * (1.0f / 32.0f);
        }

        float2 b1v = ((const float2*)mlp_b1)[tid];
        float2 w2v = ((const float2*)w2)[tid];
        float2 hv = {0.f, 0.f};
        #pragma unroll
        for (int s = 0; s < 16; s++) { hv.x += th[s].x; hv.y += th[s].y; }
        hv.x += b1v.x; hv.y += b1v.y;
        float h0 = hv.x / (1.0f + expf(-hv.x));
        float h1 = hv.y / (1.0f + expf(-hv.y));
        float mp = h0 * w2v.x + h1 * w2v.y;
        #pragma unroll
        for (int o = 16; o > 0; o >>= 1) mp += __shfl_down_sync(0xffffffffu, mp, o);
        __syncthreads();                    // orders logits[] before softmax read
        if (lane == 0) rbuf[w] = mp;
        __syncthreads();
        float mlp_out = rbuf[0];
        #pragma unroll
        for (int i = 1; i < 8; i++) mlp_out += rbuf[i];
        mlp_out += b2[0];

        float sn0 = sqrtf(sc[6]), sn1 = sqrtf(sc[7]);
        float s0 = sc[1] / fmaxf(nx * sn0, 1e-8f);
        float s1 = sc[2] / fmaxf(nx * sn1, 1e-8f);
        int best = (s1 > s0) ? 1 : 0;
        float changed = 1.0f;
        if (b > 0) {
            float pn  = sqrtf(sc[3]);
            float ps0 = sc[4] / fmaxf(pn * sn0, 1e-8f);
            float ps1 = sc[5] / fmaxf(pn * sn1, 1e-8f);
            int pbest = (ps1 > ps0) ? 1 : 0;
            changed = (best != pbest) ? 1.0f : 0.0f;
        }

        if (tid < 32) {
            float l0 = logits[tid], l1 = logits[tid + 32];
            float mx = fmaxf(l0, l1);
            #pragma unroll
            for (int o = 16; o > 0; o >>= 1) mx = fmaxf(mx, __shfl_xor_sync(0xffffffffu, mx, o));
            float e0 = expf(l0 - mx), e1 = expf(l1 - mx);
            float ssum = e0 + e1;
            float vsum = e0 * valm[tid] + e1 * valm[tid + 32];
            #pragma unroll
            for (int o = 16; o > 0; o >>= 1) {
                ssum += __shfl_down_sync(0xffffffffu, ssum, o);
                vsum += __shfl_down_sync(0xffffffffu, vsum, o);
            }
            if (tid == 0) {
                float mem_val = vsum / ssum;
                out[b]      = (changed > thr[0]) ? 1.0f : 0.0f;
                out[B_ + b] = cw[0] * mem_val + cw[1] * mlp_out + cb[0];
            }
        }
    }
}

// ---------------- launch ----------------
extern "C" void kernel_launch(void* const* d_in, const int* in_sizes, int n_in,
                              void* d_out, int out_size) {
    const float* x       = (const float*)d_in[0];
    const float* mkey0   = (const float*)d_in[1];
    const float* mkey1   = (const float*)d_in[2];
    const float* keym    = (const float*)d_in[3];
    const float* valm    = (const float*)d_in[4];
    const float* mlp_w1  = (const float*)d_in[5];
    const float* mlp_b1  = (const float*)d_in[6];
    const float* mlp_w2  = (const float*)d_in[7];
    const float* mlp_b2  = (const float*)d_in[8];
    const float* cw      = (const float*)d_in[9];
    const float* cb      = (const float*)d_in[10];
    const float* xa_w    = (const float*)d_in[11];
    const float* xa_b    = (const float*)d_in[12];
    const float* thr     = (const float*)d_in[13];
    float* out = (float*)d_out;

    cudaFuncSetAttribute(k_all, cudaFuncAttributeMaxDynamicSharedMemorySize, SMEM_BYTES);
    k_all<<<NB_, 256, SMEM_BYTES>>>(x, mkey0, mkey1, keym, valm,
                                    mlp_w1, mlp_b1, mlp_w2, mlp_b2,
                                    cw, cb, xa_w, xa_b, thr, out);
}